// round 15
// baseline (speedup 1.0000x reference)
#include <cuda_runtime.h>
#include <cuda_fp16.h>
#include <math.h>
#include <stdint.h>

#define BATCH    512
#define NTOK     100
#define HD       768
#define ID       1536
#define M_ROWS   (BATCH * NTOK)     // 51200
#define BM       64
#define ROW_BLKS (M_ROWS / BM)      // 800
#define BN       96
#define N_PASSES (ID / BN)          // 16
#define BK       64                 // K elements per stage
#define KT_PER   (HD / BK)          // 12
#define APITCH   144                // smem bytes per row (64 fp16 + 16 pad)
#define A_STAGE_B (BM * APITCH)     // 9216
#define B_STAGE_B (BN * APITCH)     // 13824
#define STAGE_B   (A_STAGE_B + B_STAGE_B)  // 23040
#define SM_B1H    (2 * STAGE_B)            // 46080 (fp16 bias, 3072 B)
#define SM_SGW    (SM_B1H + ID * 2)        // 49152 (fp32 gamma*W2, 6144 B)
#define SM_RED    (SM_SGW + ID * 4)        // 55296
#define SMEM_TOTAL (SM_RED + 2 * BM * 3 * 4)  // 56832  (fits 4 CTAs/SM)
#define LN_EPS   1e-5f

__device__ float g_c1, g_c2;

// A2: [M][768] fp16 (written by each GEMM CTA for its own 64-row slice)
__device__ __align__(16) __half A2[(size_t)M_ROWS * HD];
// Bt: [N=1536][768] fp16  (Bt[n][k] = W1[k][n])
__device__ __align__(16) __half Bt[(size_t)ID * HD];

// ------------------------------- helpers -----------------------------------
__device__ __forceinline__ uint32_t smem_u32(const void* p) {
    uint32_t a;
    asm("{ .reg .u64 t; cvta.to.shared.u64 t, %1; cvt.u32.u64 %0, t; }" : "=r"(a) : "l"(p));
    return a;
}
__device__ __forceinline__ void cp16(uint32_t dst, const void* src) {
    asm volatile("cp.async.cg.shared.global [%0], [%1], 16;" :: "r"(dst), "l"(src));
}
#define CP_COMMIT() asm volatile("cp.async.commit_group;" ::: "memory")
#define CP_WAIT1()  asm volatile("cp.async.wait_group 1;" ::: "memory")
#define CP_WAIT0()  asm volatile("cp.async.wait_group 0;" ::: "memory")

#define LDSM4(r0, r1, r2, r3, addr) \
    asm volatile("ldmatrix.sync.aligned.m8n8.x4.shared.b16 {%0,%1,%2,%3}, [%4];" \
                 : "=r"(r0), "=r"(r1), "=r"(r2), "=r"(r3) : "r"(addr))

// fp16-accumulator mma: d (2 packed half2 regs) += a x b
#define MMA16816H(d, a, bx, by) \
    asm volatile("mma.sync.aligned.m16n8k16.row.col.f16.f16.f16.f16 " \
                 "{%0,%1},{%2,%3,%4,%5},{%6,%7},{%0,%1};" \
                 : "+r"((d)[0]), "+r"((d)[1]) \
                 : "r"((a)[0]), "r"((a)[1]), "r"((a)[2]), "r"((a)[3]), "r"(bx), "r"(by))

// ------------------------------ prep kernel --------------------------------
// Coalesced tiled transpose W1[k][n] fp32 -> Bt[n][k] fp16 via smem staging.
__global__ void prep_kernel(const float* __restrict__ W1,
                            const float* __restrict__ gamma,
                            const float* __restrict__ beta,
                            const float* __restrict__ W2,
                            const float* __restrict__ b2) {
    __shared__ __half tile[64][72];
    const int tid = threadIdx.x;        // 0..255
    const int k0 = blockIdx.x * 64;
    const int n0 = blockIdx.y * 64;

    {
        int kr = tid >> 2;
        int nc = (tid & 3) * 16;
        const float4* src = (const float4*)(W1 + (size_t)(k0 + kr) * ID + n0 + nc);
#pragma unroll
        for (int q = 0; q < 4; q++) {
            float4 v = src[q];
            int n = nc + q * 4;
            tile[n + 0][kr] = __float2half_rn(v.x);
            tile[n + 1][kr] = __float2half_rn(v.y);
            tile[n + 2][kr] = __float2half_rn(v.z);
            tile[n + 3][kr] = __float2half_rn(v.w);
        }
    }
    __syncthreads();
    {
#pragma unroll
        for (int q = 0; q < 2; q++) {
            int c = tid + 256 * q;
            int nr = c >> 3;
            int kc = (c & 7) * 8;
            uint4 v = *(uint4*)&tile[nr][kc];
            *(uint4*)(Bt + (size_t)(n0 + nr) * HD + k0 + kc) = v;
        }
    }

    if (blockIdx.x == 0 && blockIdx.y == 0) {
        __shared__ float s1s[8], s2s[8];
        float c1 = 0.f, c2 = 0.f;
        for (int i = tid; i < ID; i += 256) {
            float w = W2[i];
            c1 += gamma[i] * w;
            c2 += beta[i] * w;
        }
        for (int o = 16; o; o >>= 1) {
            c1 += __shfl_xor_sync(0xffffffffu, c1, o);
            c2 += __shfl_xor_sync(0xffffffffu, c2, o);
        }
        if ((tid & 31) == 0) { s1s[tid >> 5] = c1; s2s[tid >> 5] = c2; }
        __syncthreads();
        if (tid == 0) {
            float a = 0.f, b = 0.f;
            for (int w = 0; w < 8; w++) { a += s1s[w]; b += s2s[w]; }
            g_c1 = a;
            g_c2 = b + b2[0];
        }
    }
}

// ------------------------------ GEMM stage issue ----------------------------
__device__ __forceinline__ void issue_tile(uint32_t sb, int s, int rb, int nt, int kt, int tid) {
    const __half* gA = A2 + (size_t)rb * BM * HD + kt * BK;
    uint32_t dA = sb + s * STAGE_B;
#pragma unroll
    for (int j = 0; j < 4; j++) {
        int c = tid + 128 * j;          // 0..511
        int row = c >> 3, c16 = c & 7;
        cp16(dA + row * APITCH + c16 * 16, gA + (size_t)row * HD + c16 * 8);
    }
    const __half* gB = Bt + (size_t)nt * BN * HD + kt * BK;
    uint32_t dB = sb + s * STAGE_B + A_STAGE_B;
#pragma unroll
    for (int j = 0; j < 6; j++) {
        int c = tid + 128 * j;          // 0..767
        int row = c >> 3, c16 = c & 7;
        cp16(dB + row * APITCH + c16 * 16, gB + (size_t)row * HD + c16 * 8);
    }
}

// ------------------------------ GEMM kernel --------------------------------
// 128 threads (4 warps): warp grid 2(M) x 2(N), warp tile 32x48, fp16 acc.
// 4 CTAs/SM (16 warps) — occupancy experiment enabled by fp16-acc regs.
__global__ __launch_bounds__(128, 4)
void gemm_kernel(const float* __restrict__ Vemb,
                 const float* __restrict__ b1,
                 const float* __restrict__ gamma,
                 const float* __restrict__ W2,
                 float* __restrict__ scores) {
    extern __shared__ char smem[];
    const uint32_t sb = smem_u32(smem);
    __half* b1h = (__half*)(smem + SM_B1H);
    float* sgw = (float*)(smem + SM_SGW);
    float* red = (float*)(smem + SM_RED);   // [2][64][3]
    const int tid = threadIdx.x, wid = tid >> 5, lane = tid & 31;
    const int wm = wid & 1, wn = wid >> 1;
    const int rb = blockIdx.x;

    // ---- convert this CTA's exclusive A slice: v_emb fp32 -> A2 fp16 ----
    {
        const float4* src = (const float4*)(Vemb + (size_t)rb * BM * HD);
        __half* dst = A2 + (size_t)rb * BM * HD;
#pragma unroll 4
        for (int i = tid; i < BM * HD / 4; i += 128) {
            float4 v = src[i];
            __half2 h0 = __floats2half2_rn(v.x, v.y);
            __half2 h1 = __floats2half2_rn(v.z, v.w);
            uint2 pk;
            pk.x = *(uint32_t*)&h0;
            pk.y = *(uint32_t*)&h1;
            *(uint2*)(dst + (size_t)i * 4) = pk;
        }
    }
    for (int i = tid; i < ID; i += 128) {
        b1h[i] = __float2half_rn(b1[i]);
        sgw[i] = gamma[i] * W2[i];
    }
    __threadfence_block();
    __syncthreads();

    const uint32_t a_off = (uint32_t)((wm * 32 + (lane & 15)) * APITCH + (lane >> 4) * 16);
    const uint32_t b_off = (uint32_t)(A_STAGE_B
                          + (wn * 48 + ((lane & 7) | ((lane >> 4) << 3))) * APITCH
                          + ((lane >> 3) & 1) * 16);

    uint32_t hacc[2][6][2];    // fp16 acc: 2 m16-tiles x 6 n8-tiles x 2 half2
    float s1[4], s2[4], s3[4];
#pragma unroll
    for (int r = 0; r < 4; r++) { s1[r] = 0.f; s2[r] = 0.f; s3[r] = 0.f; }

    // prologue: fill BOTH stages
    int nt_p = 0, kt_p = 0;
#pragma unroll
    for (int s = 0; s < 2; s++) {
        issue_tile(sb, s, rb, nt_p, kt_p, tid);
        CP_COMMIT();
        if (++kt_p == KT_PER) { kt_p = 0; nt_p++; }
    }

    int i = 0;
    for (int nt = 0; nt < N_PASSES; nt++) {
#pragma unroll
        for (int mt = 0; mt < 2; mt++)
#pragma unroll
            for (int j = 0; j < 6; j++) {
                hacc[mt][j][0] = 0u;
                hacc[mt][j][1] = 0u;
            }

        for (int kt = 0; kt < KT_PER; kt++, i++) {
            CP_WAIT1();
            __syncthreads();
            const uint32_t stg = sb + (uint32_t)(i & 1) * STAGE_B;

            uint32_t aa[2][2][4], bb[2][3][4];
#pragma unroll
            for (int mt = 0; mt < 2; mt++)
                LDSM4(aa[0][mt][0], aa[0][mt][1], aa[0][mt][2], aa[0][mt][3],
                      stg + a_off + mt * 16 * APITCH);
#pragma unroll
            for (int np = 0; np < 3; np++)
                LDSM4(bb[0][np][0], bb[0][np][1], bb[0][np][2], bb[0][np][3],
                      stg + b_off + np * 16 * APITCH);

#pragma unroll
            for (int k16 = 0; k16 < 4; k16++) {
                const int cur = k16 & 1, nxt = cur ^ 1;
                if (k16 < 3) {
#pragma unroll
                    for (int mt = 0; mt < 2; mt++)
                        LDSM4(aa[nxt][mt][0], aa[nxt][mt][1], aa[nxt][mt][2], aa[nxt][mt][3],
                              stg + a_off + mt * 16 * APITCH + (k16 + 1) * 32);
#pragma unroll
                    for (int np = 0; np < 3; np++)
                        LDSM4(bb[nxt][np][0], bb[nxt][np][1], bb[nxt][np][2], bb[nxt][np][3],
                              stg + b_off + np * 16 * APITCH + (k16 + 1) * 32);
                }
#pragma unroll
                for (int mt = 0; mt < 2; mt++)
#pragma unroll
                    for (int np = 0; np < 3; np++) {
                        MMA16816H(hacc[mt][2 * np],     aa[cur][mt], bb[cur][np][0], bb[cur][np][1]);
                        MMA16816H(hacc[mt][2 * np + 1], aa[cur][mt], bb[cur][np][2], bb[cur][np][3]);
                    }
            }

            __syncthreads();
            if (nt_p < N_PASSES) {
                issue_tile(sb, i & 1, rb, nt_p, kt_p, tid);
                if (++kt_p == KT_PER) { kt_p = 0; nt_p++; }
            }
            CP_COMMIT();
        }

        // ---- fused epilogue: unpack fp16 acc + bias + exact GELU + LN moments ----
        const int nb = nt * BN + wn * 48;
#pragma unroll
        for (int mt = 0; mt < 2; mt++)
#pragma unroll
            for (int j = 0; j < 6; j++)
#pragma unroll
                for (int half = 0; half < 2; half++) {
                    __half2 hv = *(__half2*)&hacc[mt][j][half];
                    float c0 = __low2float(hv);
                    float c1v = __high2float(hv);
                    int n = nb + j * 8 + (lane & 3) * 2;
                    int ridx = mt * 2 + half;
                    {
                        float h = c0 + __half2float(b1h[n]);
                        float g = 0.5f * h * (1.0f + erff(h * 0.70710678118654752f));
                        s1[ridx] += g;
                        s2[ridx] += g * g;
                        s3[ridx] += g * sgw[n];
                    }
                    {
                        float h = c1v + __half2float(b1h[n + 1]);
                        float g = 0.5f * h * (1.0f + erff(h * 0.70710678118654752f));
                        s1[ridx] += g;
                        s2[ridx] += g * g;
                        s3[ridx] += g * sgw[n + 1];
                    }
                }
    }
    CP_WAIT0();

    // quad-reduce LN moments (lanes sharing rows)
#pragma unroll
    for (int r = 0; r < 4; r++) {
        s1[r] += __shfl_xor_sync(0xffffffffu, s1[r], 1);
        s1[r] += __shfl_xor_sync(0xffffffffu, s1[r], 2);
        s2[r] += __shfl_xor_sync(0xffffffffu, s2[r], 1);
        s2[r] += __shfl_xor_sync(0xffffffffu, s2[r], 2);
        s3[r] += __shfl_xor_sync(0xffffffffu, s3[r], 1);
        s3[r] += __shfl_xor_sync(0xffffffffu, s3[r], 2);
    }
    __syncthreads();

    if ((lane & 3) == 0) {
#pragma unroll
        for (int mt = 0; mt < 2; mt++)
#pragma unroll
            for (int half = 0; half < 2; half++) {
                int ridx = mt * 2 + half;
                int rl = wm * 32 + mt * 16 + (lane >> 2) + half * 8;
                float* p = red + (wn * BM + rl) * 3;
                p[0] = s1[ridx]; p[1] = s2[ridx]; p[2] = s3[ridx];
            }
    }
    __syncthreads();

    if (tid < BM) {
        const float c1 = g_c1, c2 = g_c2, inv = 1.0f / (float)ID;
        float* p0 = red + tid * 3;
        float* p1 = red + (BM + tid) * 3;
        float t1 = p0[0] + p1[0];
        float t2 = p0[1] + p1[1];
        float t3 = p0[2] + p1[2];
        float mu   = t1 * inv;
        float var  = t2 * inv - mu * mu;
        float rstd = rsqrtf(var + LN_EPS);
        float x = rstd * (t3 - mu * c1) + c2;
        scores[rb * BM + tid] = 1.0f / (1.0f + expf(-x));
    }
}

// ------------------------------ finalize -----------------------------------
__global__ void finalize_kernel(const float* __restrict__ scores,
                                float* __restrict__ pred,
                                float* __restrict__ logits) {
    int b = blockIdx.x;
    int tid = threadIdx.x;   // 128
    float v = (tid < NTOK) ? scores[b * NTOK + tid] : 0.f;
    for (int o = 16; o; o >>= 1) v += __shfl_xor_sync(0xffffffffu, v, o);
    __shared__ float ws[4];
    __shared__ float predv;
    if ((tid & 31) == 0) ws[tid >> 5] = v;
    __syncthreads();
    if (tid == 0) {
        float s = ws[0] + ws[1] + ws[2] + ws[3];
        pred[b] = s;
        predv = s;
    }
    __syncthreads();
    if (tid < 16) {
        int aid = (int)rintf(predv);
        aid = min(max(aid, 0), 15);
        logits[b * 16 + tid] = (tid == aid) ? 1.0f : 0.0f;
    }
}

// ------------------------------ launch --------------------------------------
extern "C" void kernel_launch(void* const* d_in, const int* in_sizes, int n_in,
                              void* d_out, int out_size) {
    const float* v_emb = (const float*)d_in[0];
    const float* W1    = (const float*)d_in[1];
    const float* b1    = (const float*)d_in[2];
    const float* gamma = (const float*)d_in[3];
    const float* beta  = (const float*)d_in[4];
    const float* W2    = (const float*)d_in[5];
    const float* b2    = (const float*)d_in[6];

    float* out    = (float*)d_out;
    float* scores = out;                    // [51200]
    float* pred   = out + M_ROWS;           // [512]
    float* logits = out + M_ROWS + BATCH;   // [512*16]

    cudaFuncSetAttribute(gemm_kernel, cudaFuncAttributeMaxDynamicSharedMemorySize, SMEM_TOTAL);

    dim3 pgrid(HD / 64, ID / 64);   // 12 x 24
    prep_kernel<<<pgrid, 256>>>(W1, gamma, beta, W2, b2);
    gemm_kernel<<<ROW_BLKS, 128, SMEM_TOTAL>>>(v_emb, b1, gamma, W2, scores);
    finalize_kernel<<<BATCH, 128>>>(scores, pred, logits);
}

// round 16
// speedup vs baseline: 1.0396x; 1.0396x over previous
#include <cuda_runtime.h>
#include <cuda_fp16.h>
#include <math.h>
#include <stdint.h>

#define BATCH    512
#define NTOK     100
#define HD       768
#define ID       1536
#define M_ROWS   (BATCH * NTOK)     // 51200
#define BM       64
#define ROW_BLKS (M_ROWS / BM)      // 800
#define BN       128
#define N_PASSES (ID / BN)          // 12
#define BK       64                 // K elements per stage
#define KT_PER   (HD / BK)          // 12
#define APITCH   144                // smem bytes per row (64 fp16 + 16 pad)
#define A_STAGE_B (BM * APITCH)     // 9216
#define B_STAGE_B (BN * APITCH)     // 18432
#define STAGE_B   (A_STAGE_B + B_STAGE_B)  // 27648
#define SM_B1S    (2 * STAGE_B)            // 55296
#define SM_SGW    (SM_B1S + ID * 4)        // 61440
#define SM_RED    (SM_SGW + ID * 4)        // 67584
#define SMEM_TOTAL (SM_RED + 2 * BM * 3 * 4)  // 69120
#define LN_EPS   1e-5f

__device__ float g_c1, g_c2;

// A2: [M][768] fp16 (written by each GEMM CTA for its own 64-row slice)
__device__ __align__(16) __half A2[(size_t)M_ROWS * HD];
// Bt: [N=1536][768] fp16  (Bt[n][k] = W1[k][n])
__device__ __align__(16) __half Bt[(size_t)ID * HD];

// ------------------------------- helpers -----------------------------------
__device__ __forceinline__ uint32_t smem_u32(const void* p) {
    uint32_t a;
    asm("{ .reg .u64 t; cvta.to.shared.u64 t, %1; cvt.u32.u64 %0, t; }" : "=r"(a) : "l"(p));
    return a;
}
__device__ __forceinline__ void cp16(uint32_t dst, const void* src) {
    asm volatile("cp.async.cg.shared.global [%0], [%1], 16;" :: "r"(dst), "l"(src));
}
#define CP_COMMIT() asm volatile("cp.async.commit_group;" ::: "memory")
#define CP_WAIT1()  asm volatile("cp.async.wait_group 1;" ::: "memory")
#define CP_WAIT0()  asm volatile("cp.async.wait_group 0;" ::: "memory")

#define LDSM4(r0, r1, r2, r3, addr) \
    asm volatile("ldmatrix.sync.aligned.m8n8.x4.shared.b16 {%0,%1,%2,%3}, [%4];" \
                 : "=r"(r0), "=r"(r1), "=r"(r2), "=r"(r3) : "r"(addr))

// fp16-accumulator mma: d (2 packed half2 regs) += a x b
#define MMA16816H(d, a, bx, by) \
    asm volatile("mma.sync.aligned.m16n8k16.row.col.f16.f16.f16.f16 " \
                 "{%0,%1},{%2,%3,%4,%5},{%6,%7},{%0,%1};" \
                 : "+r"((d)[0]), "+r"((d)[1]) \
                 : "r"((a)[0]), "r"((a)[1]), "r"((a)[2]), "r"((a)[3]), "r"(bx), "r"(by))

// ------------------------------ prep kernel --------------------------------
// Coalesced tiled transpose W1[k][n] fp32 -> Bt[n][k] fp16 via smem staging.
// Grid: (HD/32) x (ID/64) = 24 x 24 = 576 blocks of 32(k) x 64(n) tiles.
__global__ void prep_kernel(const float* __restrict__ W1,
                            const float* __restrict__ gamma,
                            const float* __restrict__ beta,
                            const float* __restrict__ W2,
                            const float* __restrict__ b2) {
    __shared__ __half tile[64][40];     // 64 n-rows x 32 k + 8 pad (80B pitch)
    const int tid = threadIdx.x;        // 0..255
    const int k0 = blockIdx.x * 32;
    const int n0 = blockIdx.y * 64;

    // load 32(k) x 64(n) floats: each thread 1 k-row, 8 n (2 float4)
    {
        int kr = tid >> 3;              // 0..31
        int nc = (tid & 7) * 8;         // 0,8,...,56
        const float4* src = (const float4*)(W1 + (size_t)(k0 + kr) * ID + n0 + nc);
        float4 v0 = src[0];
        float4 v1 = src[1];
        tile[nc + 0][kr] = __float2half_rn(v0.x);
        tile[nc + 1][kr] = __float2half_rn(v0.y);
        tile[nc + 2][kr] = __float2half_rn(v0.z);
        tile[nc + 3][kr] = __float2half_rn(v0.w);
        tile[nc + 4][kr] = __float2half_rn(v1.x);
        tile[nc + 5][kr] = __float2half_rn(v1.y);
        tile[nc + 6][kr] = __float2half_rn(v1.z);
        tile[nc + 7][kr] = __float2half_rn(v1.w);
    }
    __syncthreads();

    // write out: 64 Bt rows x 32 halfs (64B) = 4 chunks of 16B each -> 256 chunks
    {
        int nr = tid >> 2;              // 0..63
        int kc = (tid & 3) * 8;         // 0,8,16,24
        uint4 v = *(uint4*)&tile[nr][kc];
        *(uint4*)(Bt + (size_t)(n0 + nr) * HD + k0 + kc) = v;
    }

    if (blockIdx.x == 0 && blockIdx.y == 0) {
        __shared__ float s1s[8], s2s[8];
        float c1 = 0.f, c2 = 0.f;
        for (int i = tid; i < ID; i += 256) {
            float w = W2[i];
            c1 += gamma[i] * w;
            c2 += beta[i] * w;
        }
        for (int o = 16; o; o >>= 1) {
            c1 += __shfl_xor_sync(0xffffffffu, c1, o);
            c2 += __shfl_xor_sync(0xffffffffu, c2, o);
        }
        if ((tid & 31) == 0) { s1s[tid >> 5] = c1; s2s[tid >> 5] = c2; }
        __syncthreads();
        if (tid == 0) {
            float a = 0.f, b = 0.f;
            for (int w = 0; w < 8; w++) { a += s1s[w]; b += s2s[w]; }
            g_c1 = a;
            g_c2 = b + b2[0];
        }
    }
}

// ------------------------------ GEMM stage issue ----------------------------
__device__ __forceinline__ void issue_tile(uint32_t sb, int s, int rb, int nt, int kt, int tid) {
    const __half* gA = A2 + (size_t)rb * BM * HD + kt * BK;
    uint32_t dA = sb + s * STAGE_B;
#pragma unroll
    for (int j = 0; j < 4; j++) {
        int c = tid + 128 * j;
        int row = c >> 3, c16 = c & 7;
        cp16(dA + row * APITCH + c16 * 16, gA + (size_t)row * HD + c16 * 8);
    }
    const __half* gB = Bt + (size_t)nt * BN * HD + kt * BK;
    uint32_t dB = sb + s * STAGE_B + A_STAGE_B;
#pragma unroll
    for (int j = 0; j < 8; j++) {
        int c = tid + 128 * j;
        int row = c >> 3, c16 = c & 7;
        cp16(dB + row * APITCH + c16 * 16, gB + (size_t)row * HD + c16 * 8);
    }
}

// ------------------------------ GEMM kernel --------------------------------
// 128 threads (4 warps): warp grid 2(M) x 2(N), warp tile 32x64,
// mma m16n8k16 f16 with fp16 accumulators. 3 CTAs/SM (proven best).
__global__ __launch_bounds__(128, 3)
void gemm_kernel(const float* __restrict__ Vemb,
                 const float* __restrict__ b1,
                 const float* __restrict__ gamma,
                 const float* __restrict__ W2,
                 float* __restrict__ scores) {
    extern __shared__ char smem[];
    const uint32_t sb = smem_u32(smem);
    float* b1s = (float*)(smem + SM_B1S);
    float* sgw = (float*)(smem + SM_SGW);
    float* red = (float*)(smem + SM_RED);   // [2][64][3]
    const int tid = threadIdx.x, wid = tid >> 5, lane = tid & 31;
    const int wm = wid & 1, wn = wid >> 1;
    const int rb = blockIdx.x;

    // ---- convert this CTA's exclusive A slice: v_emb fp32 -> A2 fp16 ----
    {
        const float4* src = (const float4*)(Vemb + (size_t)rb * BM * HD);
        __half* dst = A2 + (size_t)rb * BM * HD;
#pragma unroll 4
        for (int i = tid; i < BM * HD / 4; i += 128) {
            float4 v = src[i];
            __half2 h0 = __floats2half2_rn(v.x, v.y);
            __half2 h1 = __floats2half2_rn(v.z, v.w);
            uint2 pk;
            pk.x = *(uint32_t*)&h0;
            pk.y = *(uint32_t*)&h1;
            *(uint2*)(dst + (size_t)i * 4) = pk;
        }
    }
    for (int i = tid; i < ID; i += 128) {
        b1s[i] = b1[i];
        sgw[i] = gamma[i] * W2[i];
    }
    __threadfence_block();
    __syncthreads();

    const uint32_t a_off = (uint32_t)((wm * 32 + (lane & 15)) * APITCH + (lane >> 4) * 16);
    const uint32_t b_off = (uint32_t)(A_STAGE_B
                          + (wn * 64 + ((lane & 7) | ((lane >> 4) << 3))) * APITCH
                          + ((lane >> 3) & 1) * 16);

    uint32_t hacc[2][8][2];    // fp16 accumulators: 2 m16-tiles x 8 n8-tiles x 2 half2
    float s1[4], s2[4], s3[4];
#pragma unroll
    for (int r = 0; r < 4; r++) { s1[r] = 0.f; s2[r] = 0.f; s3[r] = 0.f; }

    // prologue: fill BOTH stages
    int nt_p = 0, kt_p = 0;
#pragma unroll
    for (int s = 0; s < 2; s++) {
        issue_tile(sb, s, rb, nt_p, kt_p, tid);
        CP_COMMIT();
        if (++kt_p == KT_PER) { kt_p = 0; nt_p++; }
    }

    int i = 0;
    for (int nt = 0; nt < N_PASSES; nt++) {
#pragma unroll
        for (int mt = 0; mt < 2; mt++)
#pragma unroll
            for (int j = 0; j < 8; j++) {
                hacc[mt][j][0] = 0u;
                hacc[mt][j][1] = 0u;
            }

        for (int kt = 0; kt < KT_PER; kt++, i++) {
            CP_WAIT1();
            __syncthreads();
            const uint32_t stg = sb + (uint32_t)(i & 1) * STAGE_B;

            uint32_t aa[2][2][4], bb[2][4][4];
#pragma unroll
            for (int mt = 0; mt < 2; mt++)
                LDSM4(aa[0][mt][0], aa[0][mt][1], aa[0][mt][2], aa[0][mt][3],
                      stg + a_off + mt * 16 * APITCH);
#pragma unroll
            for (int np = 0; np < 4; np++)
                LDSM4(bb[0][np][0], bb[0][np][1], bb[0][np][2], bb[0][np][3],
                      stg + b_off + np * 16 * APITCH);

#pragma unroll
            for (int k16 = 0; k16 < 4; k16++) {
                const int cur = k16 & 1, nxt = cur ^ 1;
                if (k16 < 3) {
#pragma unroll
                    for (int mt = 0; mt < 2; mt++)
                        LDSM4(aa[nxt][mt][0], aa[nxt][mt][1], aa[nxt][mt][2], aa[nxt][mt][3],
                              stg + a_off + mt * 16 * APITCH + (k16 + 1) * 32);
#pragma unroll
                    for (int np = 0; np < 4; np++)
                        LDSM4(bb[nxt][np][0], bb[nxt][np][1], bb[nxt][np][2], bb[nxt][np][3],
                              stg + b_off + np * 16 * APITCH + (k16 + 1) * 32);
                }
#pragma unroll
                for (int mt = 0; mt < 2; mt++)
#pragma unroll
                    for (int np = 0; np < 4; np++) {
                        MMA16816H(hacc[mt][2 * np],     aa[cur][mt], bb[cur][np][0], bb[cur][np][1]);
                        MMA16816H(hacc[mt][2 * np + 1], aa[cur][mt], bb[cur][np][2], bb[cur][np][3]);
                    }
            }

            __syncthreads();
            if (nt_p < N_PASSES) {
                issue_tile(sb, i & 1, rb, nt_p, kt_p, tid);
                if (++kt_p == KT_PER) { kt_p = 0; nt_p++; }
            }
            CP_COMMIT();
        }

        // ---- fused epilogue: unpack fp16 acc + bias + exact GELU + LN moments ----
        const int nb = nt * BN + wn * 64;
#pragma unroll
        for (int mt = 0; mt < 2; mt++)
#pragma unroll
            for (int j = 0; j < 8; j++)
#pragma unroll
                for (int half = 0; half < 2; half++) {
                    __half2 hv = *(__half2*)&hacc[mt][j][half];
                    float c0 = __low2float(hv);
                    float c1v = __high2float(hv);
                    int n = nb + j * 8 + (lane & 3) * 2;
                    int ridx = mt * 2 + half;
                    {
                        float h = c0 + b1s[n];
                        float g = 0.5f * h * (1.0f + erff(h * 0.70710678118654752f));
                        s1[ridx] += g;
                        s2[ridx] += g * g;
                        s3[ridx] += g * sgw[n];
                    }
                    {
                        float h = c1v + b1s[n + 1];
                        float g = 0.5f * h * (1.0f + erff(h * 0.70710678118654752f));
                        s1[ridx] += g;
                        s2[ridx] += g * g;
                        s3[ridx] += g * sgw[n + 1];
                    }
                }
    }
    CP_WAIT0();

    // quad-reduce LN moments (lanes sharing rows)
#pragma unroll
    for (int r = 0; r < 4; r++) {
        s1[r] += __shfl_xor_sync(0xffffffffu, s1[r], 1);
        s1[r] += __shfl_xor_sync(0xffffffffu, s1[r], 2);
        s2[r] += __shfl_xor_sync(0xffffffffu, s2[r], 1);
        s2[r] += __shfl_xor_sync(0xffffffffu, s2[r], 2);
        s3[r] += __shfl_xor_sync(0xffffffffu, s3[r], 1);
        s3[r] += __shfl_xor_sync(0xffffffffu, s3[r], 2);
    }
    __syncthreads();

    if ((lane & 3) == 0) {
#pragma unroll
        for (int mt = 0; mt < 2; mt++)
#pragma unroll
            for (int half = 0; half < 2; half++) {
                int ridx = mt * 2 + half;
                int rl = wm * 32 + mt * 16 + (lane >> 2) + half * 8;
                float* p = red + (wn * BM + rl) * 3;
                p[0] = s1[ridx]; p[1] = s2[ridx]; p[2] = s3[ridx];
            }
    }
    __syncthreads();

    if (tid < BM) {
        const float c1 = g_c1, c2 = g_c2, inv = 1.0f / (float)ID;
        float* p0 = red + tid * 3;
        float* p1 = red + (BM + tid) * 3;
        float t1 = p0[0] + p1[0];
        float t2 = p0[1] + p1[1];
        float t3 = p0[2] + p1[2];
        float mu   = t1 * inv;
        float var  = t2 * inv - mu * mu;
        float rstd = rsqrtf(var + LN_EPS);
        float x = rstd * (t3 - mu * c1) + c2;
        scores[rb * BM + tid] = 1.0f / (1.0f + expf(-x));
    }
}

// ------------------------------ finalize -----------------------------------
__global__ void finalize_kernel(const float* __restrict__ scores,
                                float* __restrict__ pred,
                                float* __restrict__ logits) {
    int b = blockIdx.x;
    int tid = threadIdx.x;   // 128
    float v = (tid < NTOK) ? scores[b * NTOK + tid] : 0.f;
    for (int o = 16; o; o >>= 1) v += __shfl_xor_sync(0xffffffffu, v, o);
    __shared__ float ws[4];
    __shared__ float predv;
    if ((tid & 31) == 0) ws[tid >> 5] = v;
    __syncthreads();
    if (tid == 0) {
        float s = ws[0] + ws[1] + ws[2] + ws[3];
        pred[b] = s;
        predv = s;
    }
    __syncthreads();
    if (tid < 16) {
        int aid = (int)rintf(predv);
        aid = min(max(aid, 0), 15);
        logits[b * 16 + tid] = (tid == aid) ? 1.0f : 0.0f;
    }
}

// ------------------------------ launch --------------------------------------
extern "C" void kernel_launch(void* const* d_in, const int* in_sizes, int n_in,
                              void* d_out, int out_size) {
    const float* v_emb = (const float*)d_in[0];
    const float* W1    = (const float*)d_in[1];
    const float* b1    = (const float*)d_in[2];
    const float* gamma = (const float*)d_in[3];
    const float* beta  = (const float*)d_in[4];
    const float* W2    = (const float*)d_in[5];
    const float* b2    = (const float*)d_in[6];

    float* out    = (float*)d_out;
    float* scores = out;                    // [51200]
    float* pred   = out + M_ROWS;           // [512]
    float* logits = out + M_ROWS + BATCH;   // [512*16]

    cudaFuncSetAttribute(gemm_kernel, cudaFuncAttributeMaxDynamicSharedMemorySize, SMEM_TOTAL);

    dim3 pgrid(HD / 32, ID / 64);   // 24 x 24 = 576 blocks
    prep_kernel<<<pgrid, 256>>>(W1, gamma, beta, W2, b2);
    gemm_kernel<<<ROW_BLKS, 128, SMEM_TOTAL>>>(v_emb, b1, gamma, W2, scores);
    finalize_kernel<<<BATCH, 128>>>(scores, pred, logits);
}

// round 17
// speedup vs baseline: 1.0560x; 1.0158x over previous
#include <cuda_runtime.h>
#include <cuda_fp16.h>
#include <math.h>
#include <stdint.h>

#define BATCH    512
#define NTOK     100
#define HD       768
#define ID       1536
#define M_ROWS   (BATCH * NTOK)     // 51200
#define BM       64
#define ROW_BLKS (M_ROWS / BM)      // 800
#define BN       128
#define N_PASSES (ID / BN)          // 12
#define BK       64                 // K elements per stage
#define KT_PER   (HD / BK)          // 12
#define APITCH   144                // smem bytes per row (64 fp16 + 16 pad)
#define A_STAGE_B (BM * APITCH)     // 9216
#define B_STAGE_B (BN * APITCH)     // 18432
#define STAGE_B   (A_STAGE_B + B_STAGE_B)  // 27648
#define SM_B1S    (2 * STAGE_B)            // 55296
#define SM_SGW    (SM_B1S + ID * 4)        // 61440
#define SM_RED    (SM_SGW + ID * 4)        // 67584
#define SMEM_TOTAL (SM_RED + 2 * BM * 3 * 4)  // 69120
#define LN_EPS   1e-5f

__device__ float g_c1, g_c2;

// A2: [M][768] fp16 (written by each GEMM CTA for its own 64-row slice)
__device__ __align__(16) __half A2[(size_t)M_ROWS * HD];
// Bt: [N=1536][768] fp16  (Bt[n][k] = W1[k][n])
__device__ __align__(16) __half Bt[(size_t)ID * HD];

// ------------------------------- helpers -----------------------------------
__device__ __forceinline__ uint32_t smem_u32(const void* p) {
    uint32_t a;
    asm("{ .reg .u64 t; cvta.to.shared.u64 t, %1; cvt.u32.u64 %0, t; }" : "=r"(a) : "l"(p));
    return a;
}
__device__ __forceinline__ void cp16(uint32_t dst, const void* src) {
    asm volatile("cp.async.cg.shared.global [%0], [%1], 16;" :: "r"(dst), "l"(src));
}
#define CP_COMMIT() asm volatile("cp.async.commit_group;" ::: "memory")
#define CP_WAIT1()  asm volatile("cp.async.wait_group 1;" ::: "memory")
#define CP_WAIT0()  asm volatile("cp.async.wait_group 0;" ::: "memory")

#define LDSM4(r0, r1, r2, r3, addr) \
    asm volatile("ldmatrix.sync.aligned.m8n8.x4.shared.b16 {%0,%1,%2,%3}, [%4];" \
                 : "=r"(r0), "=r"(r1), "=r"(r2), "=r"(r3) : "r"(addr))

// fp16-accumulator mma: d (2 packed half2 regs) += a x b
#define MMA16816H(d, a, bx, by) \
    asm volatile("mma.sync.aligned.m16n8k16.row.col.f16.f16.f16.f16 " \
                 "{%0,%1},{%2,%3,%4,%5},{%6,%7},{%0,%1};" \
                 : "+r"((d)[0]), "+r"((d)[1]) \
                 : "r"((a)[0]), "r"((a)[1]), "r"((a)[2]), "r"((a)[3]), "r"(bx), "r"(by))

// ------------------------------ prep kernel --------------------------------
// Coalesced tiled transpose W1[k][n] fp32 -> Bt[n][k] fp16 via smem staging.
__global__ void prep_kernel(const float* __restrict__ W1,
                            const float* __restrict__ gamma,
                            const float* __restrict__ beta,
                            const float* __restrict__ W2,
                            const float* __restrict__ b2) {
    __shared__ __half tile[64][40];     // 64 n-rows x 32 k + 8 pad (80B pitch)
    const int tid = threadIdx.x;        // 0..255
    const int k0 = blockIdx.x * 32;
    const int n0 = blockIdx.y * 64;

    {
        int kr = tid >> 3;              // 0..31
        int nc = (tid & 7) * 8;         // 0,8,...,56
        const float4* src = (const float4*)(W1 + (size_t)(k0 + kr) * ID + n0 + nc);
        float4 v0 = src[0];
        float4 v1 = src[1];
        tile[nc + 0][kr] = __float2half_rn(v0.x);
        tile[nc + 1][kr] = __float2half_rn(v0.y);
        tile[nc + 2][kr] = __float2half_rn(v0.z);
        tile[nc + 3][kr] = __float2half_rn(v0.w);
        tile[nc + 4][kr] = __float2half_rn(v1.x);
        tile[nc + 5][kr] = __float2half_rn(v1.y);
        tile[nc + 6][kr] = __float2half_rn(v1.z);
        tile[nc + 7][kr] = __float2half_rn(v1.w);
    }
    __syncthreads();
    {
        int nr = tid >> 2;              // 0..63
        int kc = (tid & 3) * 8;         // 0,8,16,24
        uint4 v = *(uint4*)&tile[nr][kc];
        *(uint4*)(Bt + (size_t)(n0 + nr) * HD + k0 + kc) = v;
    }

    if (blockIdx.x == 0 && blockIdx.y == 0) {
        __shared__ float s1s[8], s2s[8];
        float c1 = 0.f, c2 = 0.f;
        for (int i = tid; i < ID; i += 256) {
            float w = W2[i];
            c1 += gamma[i] * w;
            c2 += beta[i] * w;
        }
        for (int o = 16; o; o >>= 1) {
            c1 += __shfl_xor_sync(0xffffffffu, c1, o);
            c2 += __shfl_xor_sync(0xffffffffu, c2, o);
        }
        if ((tid & 31) == 0) { s1s[tid >> 5] = c1; s2s[tid >> 5] = c2; }
        __syncthreads();
        if (tid == 0) {
            float a = 0.f, b = 0.f;
            for (int w = 0; w < 8; w++) { a += s1s[w]; b += s2s[w]; }
            g_c1 = a;
            g_c2 = b + b2[0];
        }
    }
}

// ------------------------------ GEMM stage issue ----------------------------
__device__ __forceinline__ void issue_A(uint32_t sb, int s, int rb, int kt, int tid) {
    const __half* gA = A2 + (size_t)rb * BM * HD + kt * BK;
    uint32_t dA = sb + s * STAGE_B;
#pragma unroll
    for (int j = 0; j < 4; j++) {
        int c = tid + 128 * j;
        int row = c >> 3, c16 = c & 7;
        cp16(dA + row * APITCH + c16 * 16, gA + (size_t)row * HD + c16 * 8);
    }
}
__device__ __forceinline__ void issue_B(uint32_t sb, int s, int nt, int kt, int tid) {
    const __half* gB = Bt + (size_t)nt * BN * HD + kt * BK;
    uint32_t dB = sb + s * STAGE_B + A_STAGE_B;
#pragma unroll
    for (int j = 0; j < 8; j++) {
        int c = tid + 128 * j;
        int row = c >> 3, c16 = c & 7;
        cp16(dB + row * APITCH + c16 * 16, gB + (size_t)row * HD + c16 * 8);
    }
}
__device__ __forceinline__ void issue_tile(uint32_t sb, int s, int rb, int nt, int kt, int tid) {
    issue_A(sb, s, rb, kt, tid);
    issue_B(sb, s, nt, kt, tid);
}

// ------------------------------ GEMM kernel --------------------------------
// 128 threads (4 warps): warp grid 2(M) x 2(N), warp tile 32x64,
// mma m16n8k16 f16 with fp16 accumulators, 3 CTAs/SM.
// Prologue overlap: B copies for both stages are issued BEFORE the A
// conversion; A copies issued after fence+sync. 4 prologue cp.async groups.
__global__ __launch_bounds__(128, 3)
void gemm_kernel(const float* __restrict__ Vemb,
                 const float* __restrict__ b1,
                 const float* __restrict__ gamma,
                 const float* __restrict__ W2,
                 float* __restrict__ scores) {
    extern __shared__ char smem[];
    const uint32_t sb = smem_u32(smem);
    float* b1s = (float*)(smem + SM_B1S);
    float* sgw = (float*)(smem + SM_SGW);
    float* red = (float*)(smem + SM_RED);   // [2][64][3]
    const int tid = threadIdx.x, wid = tid >> 5, lane = tid & 31;
    const int wm = wid & 1, wn = wid >> 1;
    const int rb = blockIdx.x;

    // ---- prologue groups g0,g1: B copies for stages 0,1 (independent of A2)
    issue_B(sb, 0, /*nt=*/0, /*kt=*/0, tid);
    CP_COMMIT();                                   // g0
    issue_B(sb, 1, /*nt=*/0, /*kt=*/1, tid);
    CP_COMMIT();                                   // g1

    // ---- convert this CTA's exclusive A slice (overlaps with B copies) ----
    {
        const float4* src = (const float4*)(Vemb + (size_t)rb * BM * HD);
        __half* dst = A2 + (size_t)rb * BM * HD;
#pragma unroll 4
        for (int i = tid; i < BM * HD / 4; i += 128) {
            float4 v = src[i];
            __half2 h0 = __floats2half2_rn(v.x, v.y);
            __half2 h1 = __floats2half2_rn(v.z, v.w);
            uint2 pk;
            pk.x = *(uint32_t*)&h0;
            pk.y = *(uint32_t*)&h1;
            *(uint2*)(dst + (size_t)i * 4) = pk;
        }
    }
    for (int i = tid; i < ID; i += 128) {
        b1s[i] = b1[i];
        sgw[i] = gamma[i] * W2[i];
    }
    __threadfence_block();
    __syncthreads();   // A2 slice + tables visible CTA-wide before A cp.async

    // ---- prologue groups g2,g3: A copies for stages 0,1 ----
    issue_A(sb, 0, rb, /*kt=*/0, tid);
    CP_COMMIT();                                   // g2
    issue_A(sb, 1, rb, /*kt=*/1, tid);
    CP_COMMIT();                                   // g3
    // stage0 = g0+g2, stage1 = g1+g3. CP_WAIT1 at i=0 drains g0..g2 (stage0
    // ready, g3 pending); steady-state 1-group-per-iter thereafter.

    const uint32_t a_off = (uint32_t)((wm * 32 + (lane & 15)) * APITCH + (lane >> 4) * 16);
    const uint32_t b_off = (uint32_t)(A_STAGE_B
                          + (wn * 64 + ((lane & 7) | ((lane >> 4) << 3))) * APITCH
                          + ((lane >> 3) & 1) * 16);

    uint32_t hacc[2][8][2];    // fp16 accumulators: 2 m16-tiles x 8 n8-tiles x 2 half2
    float s1[4], s2[4], s3[4];
#pragma unroll
    for (int r = 0; r < 4; r++) { s1[r] = 0.f; s2[r] = 0.f; s3[r] = 0.f; }

    int nt_p = 0, kt_p = 2;    // prologue consumed (nt0,kt0) and (nt0,kt1)

    int i = 0;
    for (int nt = 0; nt < N_PASSES; nt++) {
#pragma unroll
        for (int mt = 0; mt < 2; mt++)
#pragma unroll
            for (int j = 0; j < 8; j++) {
                hacc[mt][j][0] = 0u;
                hacc[mt][j][1] = 0u;
            }

        for (int kt = 0; kt < KT_PER; kt++, i++) {
            CP_WAIT1();
            __syncthreads();
            const uint32_t stg = sb + (uint32_t)(i & 1) * STAGE_B;

            uint32_t aa[2][2][4], bb[2][4][4];
#pragma unroll
            for (int mt = 0; mt < 2; mt++)
                LDSM4(aa[0][mt][0], aa[0][mt][1], aa[0][mt][2], aa[0][mt][3],
                      stg + a_off + mt * 16 * APITCH);
#pragma unroll
            for (int np = 0; np < 4; np++)
                LDSM4(bb[0][np][0], bb[0][np][1], bb[0][np][2], bb[0][np][3],
                      stg + b_off + np * 16 * APITCH);

#pragma unroll
            for (int k16 = 0; k16 < 4; k16++) {
                const int cur = k16 & 1, nxt = cur ^ 1;
                if (k16 < 3) {
#pragma unroll
                    for (int mt = 0; mt < 2; mt++)
                        LDSM4(aa[nxt][mt][0], aa[nxt][mt][1], aa[nxt][mt][2], aa[nxt][mt][3],
                              stg + a_off + mt * 16 * APITCH + (k16 + 1) * 32);
#pragma unroll
                    for (int np = 0; np < 4; np++)
                        LDSM4(bb[nxt][np][0], bb[nxt][np][1], bb[nxt][np][2], bb[nxt][np][3],
                              stg + b_off + np * 16 * APITCH + (k16 + 1) * 32);
                }
#pragma unroll
                for (int mt = 0; mt < 2; mt++)
#pragma unroll
                    for (int np = 0; np < 4; np++) {
                        MMA16816H(hacc[mt][2 * np],     aa[cur][mt], bb[cur][np][0], bb[cur][np][1]);
                        MMA16816H(hacc[mt][2 * np + 1], aa[cur][mt], bb[cur][np][2], bb[cur][np][3]);
                    }
            }

            __syncthreads();
            if (nt_p < N_PASSES) {
                issue_tile(sb, i & 1, rb, nt_p, kt_p, tid);
                if (++kt_p == KT_PER) { kt_p = 0; nt_p++; }
            }
            CP_COMMIT();
        }

        // ---- fused epilogue: unpack fp16 acc + bias + exact GELU + LN moments ----
        const int nb = nt * BN + wn * 64;
#pragma unroll
        for (int mt = 0; mt < 2; mt++)
#pragma unroll
            for (int j = 0; j < 8; j++)
#pragma unroll
                for (int half = 0; half < 2; half++) {
                    __half2 hv = *(__half2*)&hacc[mt][j][half];
                    float c0 = __low2float(hv);
                    float c1v = __high2float(hv);
                    int n = nb + j * 8 + (lane & 3) * 2;
                    int ridx = mt * 2 + half;
                    {
                        float h = c0 + b1s[n];
                        float g = 0.5f * h * (1.0f + erff(h * 0.70710678118654752f));
                        s1[ridx] += g;
                        s2[ridx] += g * g;
                        s3[ridx] += g * sgw[n];
                    }
                    {
                        float h = c1v + b1s[n + 1];
                        float g = 0.5f * h * (1.0f + erff(h * 0.70710678118654752f));
                        s1[ridx] += g;
                        s2[ridx] += g * g;
                        s3[ridx] += g * sgw[n + 1];
                    }
                }
    }
    CP_WAIT0();

    // quad-reduce LN moments (lanes sharing rows)
#pragma unroll
    for (int r = 0; r < 4; r++) {
        s1[r] += __shfl_xor_sync(0xffffffffu, s1[r], 1);
        s1[r] += __shfl_xor_sync(0xffffffffu, s1[r], 2);
        s2[r] += __shfl_xor_sync(0xffffffffu, s2[r], 1);
        s2[r] += __shfl_xor_sync(0xffffffffu, s2[r], 2);
        s3[r] += __shfl_xor_sync(0xffffffffu, s3[r], 1);
        s3[r] += __shfl_xor_sync(0xffffffffu, s3[r], 2);
    }
    __syncthreads();

    if ((lane & 3) == 0) {
#pragma unroll
        for (int mt = 0; mt < 2; mt++)
#pragma unroll
            for (int half = 0; half < 2; half++) {
                int ridx = mt * 2 + half;
                int rl = wm * 32 + mt * 16 + (lane >> 2) + half * 8;
                float* p = red + (wn * BM + rl) * 3;
                p[0] = s1[ridx]; p[1] = s2[ridx]; p[2] = s3[ridx];
            }
    }
    __syncthreads();

    if (tid < BM) {
        const float c1 = g_c1, c2 = g_c2, inv = 1.0f / (float)ID;
        float* p0 = red + tid * 3;
        float* p1 = red + (BM + tid) * 3;
        float t1 = p0[0] + p1[0];
        float t2 = p0[1] + p1[1];
        float t3 = p0[2] + p1[2];
        float mu   = t1 * inv;
        float var  = t2 * inv - mu * mu;
        float rstd = rsqrtf(var + LN_EPS);
        float x = rstd * (t3 - mu * c1) + c2;
        scores[rb * BM + tid] = 1.0f / (1.0f + expf(-x));
    }
}

// ------------------------------ finalize -----------------------------------
__global__ void finalize_kernel(const float* __restrict__ scores,
                                float* __restrict__ pred,
                                float* __restrict__ logits) {
    int b = blockIdx.x;
    int tid = threadIdx.x;   // 128
    float v = (tid < NTOK) ? scores[b * NTOK + tid] : 0.f;
    for (int o = 16; o; o >>= 1) v += __shfl_xor_sync(0xffffffffu, v, o);
    __shared__ float ws[4];
    __shared__ float predv;
    if ((tid & 31) == 0) ws[tid >> 5] = v;
    __syncthreads();
    if (tid == 0) {
        float s = ws[0] + ws[1] + ws[2] + ws[3];
        pred[b] = s;
        predv = s;
    }
    __syncthreads();
    if (tid < 16) {
        int aid = (int)rintf(predv);
        aid = min(max(aid, 0), 15);
        logits[b * 16 + tid] = (tid == aid) ? 1.0f : 0.0f;
    }
}

// ------------------------------ launch --------------------------------------
extern "C" void kernel_launch(void* const* d_in, const int* in_sizes, int n_in,
                              void* d_out, int out_size) {
    const float* v_emb = (const float*)d_in[0];
    const float* W1    = (const float*)d_in[1];
    const float* b1    = (const float*)d_in[2];
    const float* gamma = (const float*)d_in[3];
    const float* beta  = (const float*)d_in[4];
    const float* W2    = (const float*)d_in[5];
    const float* b2    = (const float*)d_in[6];

    float* out    = (float*)d_out;
    float* scores = out;                    // [51200]
    float* pred   = out + M_ROWS;           // [512]
    float* logits = out + M_ROWS + BATCH;   // [512*16]

    cudaFuncSetAttribute(gemm_kernel, cudaFuncAttributeMaxDynamicSharedMemorySize, SMEM_TOTAL);

    dim3 pgrid(HD / 32, ID / 64);   // 24 x 24 = 576 blocks
    prep_kernel<<<pgrid, 256>>>(W1, gamma, beta, W2, b2);
    gemm_kernel<<<ROW_BLKS, 128, SMEM_TOTAL>>>(v_emb, b1, gamma, W2, scores);
    finalize_kernel<<<BATCH, 128>>>(scores, pred, logits);
}